// round 16
// baseline (speedup 1.0000x reference)
#include <cuda_runtime.h>
#include <math.h>

// Problem constants
#define BB 4096
#define FF 2048
#define TT 16
#define KK 8
#define FT 32                  // f per stage (16 KB)
#define NSPLIT 4               // f-splits
#define FQ (FF / NSPLIT)       // 512 f per block
#define NTILES (FQ / FT)       // 16 tiles per block
#define STAGES 3

// Reorganized W: [f][j][t], entry = (W[2j,t,f], W[2j+1,t,f]) as float2. 1 MB.
__device__ float2 g_Wr[FF * 4 * TT];
// Partial logits per f-split, layout identical to out [B,T,K] (float4 quads). 8 MB.
__device__ float4 g_part[NSPLIT][BB * TT * KK / 4];

// ---------------------------------------------------------------------------
// Kernel 0: reorganize W [K,T,F] -> g_Wr [F][4][16]. Lanes map to f (coalesced
// 128B reads); writes scatter at stride 512B (cheap, store path).
// ---------------------------------------------------------------------------
__global__ void reorg_W_kernel(const float* __restrict__ W) {
    int gid = blockIdx.x * 256 + threadIdx.x;   // 0 .. 131071
    int flane = gid & 31;
    int t  = (gid >> 5) & 15;
    int j  = (gid >> 9) & 3;
    int fw = gid >> 11;                         // 0 .. 63
    int f  = fw * 32 + flane;
    float lo = W[(2 * j)     * TT * FF + t * FF + f];
    float hi = W[(2 * j + 1) * TT * FF + t * FF + f];
    g_Wr[f * 64 + j * 16 + t] = make_float2(lo, hi);
}

// ---------------------------------------------------------------------------
// Helpers
// ---------------------------------------------------------------------------
__device__ __forceinline__ unsigned long long pack2(float x) {
    unsigned long long r;
    asm("mov.b64 %0, {%1, %1};" : "=l"(r) : "r"(__float_as_uint(x)));
    return r;
}
__device__ __forceinline__ void ffma2(unsigned long long& acc,
                                      unsigned long long a,
                                      unsigned long long w) {
    asm("fma.rn.f32x2 %0, %1, %2, %0;" : "+l"(acc) : "l"(a), "l"(w));
}
__device__ __forceinline__ void cpa16(void* dst_smem, const void* src) {
    unsigned s = (unsigned)__cvta_generic_to_shared(dst_smem);
    asm volatile("cp.async.cg.shared.global [%0], [%1], 16;" :: "r"(s), "l"(src));
}
__device__ __forceinline__ void cp_commit() {
    asm volatile("cp.async.commit_group;");
}
__device__ __forceinline__ float sigmoidf_(float x) {
    return 1.0f / (1.0f + __expf(-x));
}

// ---------------------------------------------------------------------------
// Main kernel: 512 blocks (128 b-blocks x 4 f-splits), 256 threads, occ 3.
// thread: t = tid&15, bsub = tid>>4; rows (base+bsub, base+16+bsub).
// 3-stage cp.async pipeline, ONE __syncthreads per tile.
// ---------------------------------------------------------------------------
__global__ __launch_bounds__(256, 3)
void temporal_partial_kernel(const float* __restrict__ h) {
    __shared__ float4 buf[STAGES][FT * 32];   // 3 x 16 KB

    const int tid  = threadIdx.x;
    const int t    = tid & 15;
    const int bsub = tid >> 4;
    const int bblk = blockIdx.x & 127;
    const int yq   = blockIdx.x >> 7;          // f-split 0..3

    const int bA = bblk * 32 + bsub;
    const int bB = bA + 16;

    const float* hA = h + (size_t)bA * (FF * TT) + (size_t)yq * FQ * TT + t;
    const float* hB = h + (size_t)bB * (FF * TT) + (size_t)yq * FQ * TT + t;

    // W source for this f-split: 32 float4 per f
    const float4* wsrc = reinterpret_cast<const float4*>(g_Wr)
                         + (size_t)yq * FQ * 32;

    unsigned long long accA[4] = {0ull, 0ull, 0ull, 0ull};
    unsigned long long accB[4] = {0ull, 0ull, 0ull, 0ull};

    // Prologue: stage tiles 0 and 1 (each 1024 float4; 256 thr x 4)
#pragma unroll
    for (int j = 0; j < 4; j++)
        cpa16(&buf[0][tid + 256 * j], wsrc + tid + 256 * j);
    cp_commit();
#pragma unroll
    for (int j = 0; j < 4; j++)
        cpa16(&buf[1][tid + 256 * j], wsrc + 1024 + tid + 256 * j);
    cp_commit();

    for (int tile = 0; tile < NTILES; tile++) {
        if (tile < NTILES - 1) {
            asm volatile("cp.async.wait_group 1;");
        } else {
            asm volatile("cp.async.wait_group 0;");
        }
        // Single barrier: publishes tile's data to all threads AND guarantees
        // everyone finished computing tile-1, so stage (tile+2)%3 is reusable.
        __syncthreads();

        if (tile + 2 < NTILES) {
            const float4* src = wsrc + (size_t)(tile + 2) * 1024;
            float4* dst = buf[(tile + 2) % STAGES];
#pragma unroll
            for (int j = 0; j < 4; j++)
                cpa16(&dst[tid + 256 * j], src + tid + 256 * j);
            cp_commit();
        }

        const unsigned long long* wq =
            reinterpret_cast<const unsigned long long*>(buf[tile % STAGES]);
        const float* pA = hA + (size_t)tile * FT * TT;
        const float* pB = hB + (size_t)tile * FT * TT;

#pragma unroll 8
        for (int fl = 0; fl < FT; fl++) {
            unsigned long long aa = pack2(__ldg(pA + fl * TT));
            unsigned long long cc = pack2(__ldg(pB + fl * TT));
            unsigned long long w0 = wq[fl * 64 + t];
            unsigned long long w1 = wq[fl * 64 + 16 + t];
            unsigned long long w2 = wq[fl * 64 + 32 + t];
            unsigned long long w3 = wq[fl * 64 + 48 + t];
            ffma2(accA[0], aa, w0);
            ffma2(accA[1], aa, w1);
            ffma2(accA[2], aa, w2);
            ffma2(accA[3], aa, w3);
            ffma2(accB[0], cc, w0);
            ffma2(accB[1], cc, w1);
            ffma2(accB[2], cc, w2);
            ffma2(accB[3], cc, w3);
        }
    }

    // Write partials: two float4 per row, layout [B,T,K]
    float2* a = reinterpret_cast<float2*>(accA);
    float2* c = reinterpret_cast<float2*>(accB);
    float4* dstA = &g_part[yq][(size_t)(bA * TT + t) * 2];
    float4* dstB = &g_part[yq][(size_t)(bB * TT + t) * 2];
    dstA[0] = make_float4(a[0].x, a[0].y, a[1].x, a[1].y);
    dstA[1] = make_float4(a[2].x, a[2].y, a[3].x, a[3].y);
    dstB[0] = make_float4(c[0].x, c[0].y, c[1].x, c[1].y);
    dstB[1] = make_float4(c[2].x, c[2].y, c[3].x, c[3].y);
}

// ---------------------------------------------------------------------------
// Combine: out = sigmoid(part0+part1+part2+part3 + bias), float4 per thread.
// ---------------------------------------------------------------------------
__global__ void combine_kernel(const float* __restrict__ bias,
                               float4* __restrict__ out) {
    int u = blockIdx.x * blockDim.x + threadIdx.x;   // 0 .. 131071
    float4 p0 = g_part[0][u];
    float4 p1 = g_part[1][u];
    float4 p2 = g_part[2][u];
    float4 p3 = g_part[3][u];
    int half = u & 1;
    int t = (u >> 1) & 15;
    int k0 = half * 4;
    float4 r;
    r.x = sigmoidf_(p0.x + p1.x + p2.x + p3.x + __ldg(bias + (k0 + 0) * TT + t));
    r.y = sigmoidf_(p0.y + p1.y + p2.y + p3.y + __ldg(bias + (k0 + 1) * TT + t));
    r.z = sigmoidf_(p0.z + p1.z + p2.z + p3.z + __ldg(bias + (k0 + 2) * TT + t));
    r.w = sigmoidf_(p0.w + p1.w + p2.w + p3.w + __ldg(bias + (k0 + 3) * TT + t));
    out[u] = r;
}

// ---------------------------------------------------------------------------
// Launch. Inputs: h_ens [B,F,T] f32, W [K,T,F] f32, b [K,T] f32. Out [B,T,K].
// ---------------------------------------------------------------------------
extern "C" void kernel_launch(void* const* d_in, const int* in_sizes, int n_in,
                              void* d_out, int out_size) {
    const float* h    = (const float*)d_in[0];
    const float* W    = (const float*)d_in[1];
    const float* bias = (const float*)d_in[2];
    float4* out       = (float4*)d_out;

    reorg_W_kernel<<<512, 256>>>(W);
    temporal_partial_kernel<<<512, 256>>>(h);
    combine_kernel<<<512, 256>>>(bias, out);
}

// round 17
// speedup vs baseline: 1.1496x; 1.1496x over previous
#include <cuda_runtime.h>
#include <math.h>

// Problem constants
#define BB 4096
#define FF 2048
#define TT 16
#define KK 8
#define FT 32                  // f per stage (16 KB)
#define NSPLIT 4               // f-splits
#define FQ (FF / NSPLIT)       // 512 f per block
#define NTILES (FQ / FT)       // 16 tiles per block
#define STAGES 3

// Reorganized W: [f][k][tp], entry = (W[k,2tp,f], W[k,2tp+1,f]) as float2. 1 MB.
__device__ float2 g_Wr[FF * KK * 8];
// Partial logits per f-split, layout identical to out [B,T,K] (float4 quads). 8 MB.
__device__ float4 g_part[NSPLIT][BB * TT * KK / 4];

// ---------------------------------------------------------------------------
// Kernel 0: reorganize W [K,T,F] -> g_Wr [F][K][8] (t-pairs packed in float2).
// Lanes map to f (coalesced 128B reads).
// ---------------------------------------------------------------------------
__global__ void reorg_W_kernel(const float* __restrict__ W) {
    int gid = blockIdx.x * 256 + threadIdx.x;   // 0 .. 131071
    int flane = gid & 31;
    int tp = (gid >> 5) & 7;
    int k  = (gid >> 8) & 7;
    int fw = gid >> 11;                         // 0 .. 63
    int f  = fw * 32 + flane;
    float lo = W[k * TT * FF + (2 * tp)     * FF + f];
    float hi = W[k * TT * FF + (2 * tp + 1) * FF + f];
    g_Wr[f * 64 + k * 8 + tp] = make_float2(lo, hi);
}

// ---------------------------------------------------------------------------
// Helpers
// ---------------------------------------------------------------------------
__device__ __forceinline__ void ffma2(unsigned long long& acc,
                                      unsigned long long a,
                                      unsigned long long w) {
    asm("fma.rn.f32x2 %0, %1, %2, %0;" : "+l"(acc) : "l"(a), "l"(w));
}
__device__ __forceinline__ void cpa16(void* dst_smem, const void* src) {
    unsigned s = (unsigned)__cvta_generic_to_shared(dst_smem);
    asm volatile("cp.async.cg.shared.global [%0], [%1], 16;" :: "r"(s), "l"(src));
}
__device__ __forceinline__ void cp_commit() {
    asm volatile("cp.async.commit_group;");
}
__device__ __forceinline__ float sigmoidf_(float x) {
    return 1.0f / (1.0f + __expf(-x));
}

// ---------------------------------------------------------------------------
// Main kernel: 256 blocks (64 b-blocks x 4 f-splits), 256 threads, occ 2.
// thread: tp = tid&7 (t-pair), bsub = tid>>3; rows (bblk*64+bsub, +32).
// Each h load is LDG.64 (t,t+1); f32x2 FMA pairs over t.
// 3-stage cp.async pipeline, ONE __syncthreads per tile, FULL unroll.
// ---------------------------------------------------------------------------
__global__ __launch_bounds__(256, 2)
void temporal_partial_kernel(const float* __restrict__ h) {
    __shared__ float4 buf[STAGES][FT * 32];   // 3 x 16 KB

    const int tid  = threadIdx.x;
    const int tp   = tid & 7;
    const int bsub = tid >> 3;                 // 0..31
    const int bblk = blockIdx.x & 63;
    const int yq   = blockIdx.x >> 6;          // f-split 0..3

    const int bA = bblk * 64 + bsub;
    const int bB = bA + 32;

    const float* hA = h + (size_t)bA * (FF * TT) + (size_t)yq * FQ * TT + tp * 2;
    const float* hB = h + (size_t)bB * (FF * TT) + (size_t)yq * FQ * TT + tp * 2;

    // W source for this f-split: 32 float4 per f
    const float4* wsrc = reinterpret_cast<const float4*>(g_Wr)
                         + (size_t)yq * FQ * 32;

    unsigned long long accA[8] = {0,0,0,0,0,0,0,0};
    unsigned long long accB[8] = {0,0,0,0,0,0,0,0};

    // Prologue: stage tiles 0 and 1 (each 1024 float4; 256 thr x 4)
#pragma unroll
    for (int j = 0; j < 4; j++)
        cpa16(&buf[0][tid + 256 * j], wsrc + tid + 256 * j);
    cp_commit();
#pragma unroll
    for (int j = 0; j < 4; j++)
        cpa16(&buf[1][tid + 256 * j], wsrc + 1024 + tid + 256 * j);
    cp_commit();

    for (int tile = 0; tile < NTILES; tile++) {
        if (tile < NTILES - 1) {
            asm volatile("cp.async.wait_group 1;");
        } else {
            asm volatile("cp.async.wait_group 0;");
        }
        // Single barrier: publishes this tile AND retires stage (tile+2)%3.
        __syncthreads();

        if (tile + 2 < NTILES) {
            const float4* src = wsrc + (size_t)(tile + 2) * 1024;
            float4* dst = buf[(tile + 2) % STAGES];
#pragma unroll
            for (int j = 0; j < 4; j++)
                cpa16(&dst[tid + 256 * j], src + tid + 256 * j);
            cp_commit();
        }

        const unsigned long long* wq =
            reinterpret_cast<const unsigned long long*>(buf[tile % STAGES]);
        const float* pA = hA + (size_t)tile * FT * TT;
        const float* pB = hB + (size_t)tile * FT * TT;

#pragma unroll
        for (int fl = 0; fl < FT; fl++) {
            unsigned long long aa =
                *reinterpret_cast<const unsigned long long*>(pA + fl * TT);
            unsigned long long cc =
                *reinterpret_cast<const unsigned long long*>(pB + fl * TT);
#pragma unroll
            for (int k = 0; k < KK; k++) {
                unsigned long long w = wq[fl * 64 + k * 8 + tp];
                ffma2(accA[k], aa, w);
                ffma2(accB[k], cc, w);
            }
        }
    }

    // Write partials: acc[k] = (logit(t0), logit(t1)). Layout [B,T,K].
    const int t0 = 2 * tp, t1 = 2 * tp + 1;
    float2* a = reinterpret_cast<float2*>(accA);
    float2* c = reinterpret_cast<float2*>(accB);
    float4* gp = g_part[yq];
    gp[((size_t)bA * TT + t0) * 2]     = make_float4(a[0].x, a[1].x, a[2].x, a[3].x);
    gp[((size_t)bA * TT + t0) * 2 + 1] = make_float4(a[4].x, a[5].x, a[6].x, a[7].x);
    gp[((size_t)bA * TT + t1) * 2]     = make_float4(a[0].y, a[1].y, a[2].y, a[3].y);
    gp[((size_t)bA * TT + t1) * 2 + 1] = make_float4(a[4].y, a[5].y, a[6].y, a[7].y);
    gp[((size_t)bB * TT + t0) * 2]     = make_float4(c[0].x, c[1].x, c[2].x, c[3].x);
    gp[((size_t)bB * TT + t0) * 2 + 1] = make_float4(c[4].x, c[5].x, c[6].x, c[7].x);
    gp[((size_t)bB * TT + t1) * 2]     = make_float4(c[0].y, c[1].y, c[2].y, c[3].y);
    gp[((size_t)bB * TT + t1) * 2 + 1] = make_float4(c[4].y, c[5].y, c[6].y, c[7].y);
}

// ---------------------------------------------------------------------------
// Combine: out = sigmoid(sum of 4 partials + bias), float4 per thread.
// ---------------------------------------------------------------------------
__global__ void combine_kernel(const float* __restrict__ bias,
                               float4* __restrict__ out) {
    int u = blockIdx.x * blockDim.x + threadIdx.x;   // 0 .. 131071
    float4 p0 = g_part[0][u];
    float4 p1 = g_part[1][u];
    float4 p2 = g_part[2][u];
    float4 p3 = g_part[3][u];
    int half = u & 1;
    int t = (u >> 1) & 15;
    int k0 = half * 4;
    float4 r;
    r.x = sigmoidf_(p0.x + p1.x + p2.x + p3.x + __ldg(bias + (k0 + 0) * TT + t));
    r.y = sigmoidf_(p0.y + p1.y + p2.y + p3.y + __ldg(bias + (k0 + 1) * TT + t));
    r.z = sigmoidf_(p0.z + p1.z + p2.z + p3.z + __ldg(bias + (k0 + 2) * TT + t));
    r.w = sigmoidf_(p0.w + p1.w + p2.w + p3.w + __ldg(bias + (k0 + 3) * TT + t));
    out[u] = r;
}

// ---------------------------------------------------------------------------
// Launch. Inputs: h_ens [B,F,T] f32, W [K,T,F] f32, b [K,T] f32. Out [B,T,K].
// ---------------------------------------------------------------------------
extern "C" void kernel_launch(void* const* d_in, const int* in_sizes, int n_in,
                              void* d_out, int out_size) {
    const float* h    = (const float*)d_in[0];
    const float* W    = (const float*)d_in[1];
    const float* bias = (const float*)d_in[2];
    float4* out       = (float4*)d_out;

    reorg_W_kernel<<<512, 256>>>(W);
    temporal_partial_kernel<<<256, 256>>>(h);
    combine_kernel<<<512, 256>>>(bias, out);
}